// round 13
// baseline (speedup 1.0000x reference)
#include <cuda_runtime.h>
#include <cuda_fp16.h>
#include <cstdint>
#include <math.h>

#define NTOK 8192
#define HD   1024
#define ID   4096
#define NE   8
#define NPAD 9216        // NTOK + NE*128 slack for per-expert padding
#define YT   72          // NPAD/128 row tiles
#define YH   36          // half

// ---------------- scratch (static device globals; no allocs) ----------------
__device__ __align__(256) __half g_W1h[(size_t)NE * HD * ID];   // 64 MB  [E][H][I]
__device__ __align__(256) __half g_Woh[(size_t)ID * HD];        // 8 MB   [I][H]
__device__ __align__(256) __half g_xh[(size_t)NTOK * HD];       // 16 MB  UNPERMUTED fp16 activations
__device__ __align__(256) __half g_inter[(size_t)NPAD * ID];    // 75.5 MB padded-permuted
__device__ __align__(256) __half g_yh[(size_t)NPAD * HD];       // 18.9 MB padded-permuted, +bo, fp16
__device__ int g_expert[NTOK];
__device__ int g_perm[NPAD];     // padded slots = -1
__device__ int g_counts[NE];
__device__ int g_offsets[NE + 1];  // PADDED offsets (each multiple of 128)
__device__ int g_cursor[NE];

// ---------------- helpers ----------------
__device__ __forceinline__ void cpa16(uint32_t s, const void* g) {
    asm volatile("cp.async.cg.shared.global [%0], [%1], 16;" :: "r"(s), "l"(g));
}
__device__ __forceinline__ void ldsm4(uint32_t& r0, uint32_t& r1, uint32_t& r2, uint32_t& r3, uint32_t a) {
    asm volatile("ldmatrix.sync.aligned.m8n8.x4.shared.b16 {%0,%1,%2,%3}, [%4];"
                 : "=r"(r0), "=r"(r1), "=r"(r2), "=r"(r3) : "r"(a));
}
__device__ __forceinline__ void ldsm4t(uint32_t& r0, uint32_t& r1, uint32_t& r2, uint32_t& r3, uint32_t a) {
    asm volatile("ldmatrix.sync.aligned.m8n8.x4.trans.shared.b16 {%0,%1,%2,%3}, [%4];"
                 : "=r"(r0), "=r"(r1), "=r"(r2), "=r"(r3) : "r"(a));
}
__device__ __forceinline__ void mma16816(float c[4], const uint32_t a[4], const uint32_t b[2]) {
    asm volatile("mma.sync.aligned.m16n8k16.row.col.f32.f16.f16.f32 "
                 "{%0,%1,%2,%3}, {%4,%5,%6,%7}, {%8,%9}, {%0,%1,%2,%3};"
                 : "+f"(c[0]), "+f"(c[1]), "+f"(c[2]), "+f"(c[3])
                 : "r"(a[0]), "r"(a[1]), "r"(a[2]), "r"(a[3]), "r"(b[0]), "r"(b[1]));
}
__device__ __forceinline__ float gelu_exact(float v) {
    return 0.5f * v * (1.0f + erff(v * 0.70710678118654752f));
}

// ---------------- init: counters + perm (stream s1, before router) ----------------
__global__ void init_kernel() {
    int i = blockIdx.x * 256 + threadIdx.x;
    if (i < NPAD) g_perm[i] = -1;
    if (i < NE) { g_counts[i] = 0; g_cursor[i] = 0; }
}

// ---------------- convert: fp32 -> fp16 (stream 0, overlaps router/scatter) ----------------
__global__ void convert_kernel(const float4* __restrict__ W1, const float4* __restrict__ Wo,
                               const float4* __restrict__ x) {
    size_t i = (size_t)blockIdx.x * blockDim.x + threadIdx.x;
    const size_t n1 = (size_t)NE * HD * ID / 4;      // 8388608
    const size_t n2 = (size_t)ID * HD / 4;           // 1048576
    const size_t n3 = (size_t)NTOK * HD / 4;         // 2097152
    if (i < n1) {
        float4 v = W1[i];
        __half2* d = (__half2*)g_W1h;
        d[2 * i]     = __floats2half2_rn(v.x, v.y);
        d[2 * i + 1] = __floats2half2_rn(v.z, v.w);
    } else if (i < n1 + n2) {
        size_t j = i - n1;
        float4 v = Wo[j];
        __half2* d = (__half2*)g_Woh;
        d[2 * j]     = __floats2half2_rn(v.x, v.y);
        d[2 * j + 1] = __floats2half2_rn(v.z, v.w);
    } else if (i < n1 + n2 + n3) {
        size_t j = i - n1 - n2;
        float4 v = x[j];
        __half2* d = (__half2*)g_xh;
        d[2 * j]     = __floats2half2_rn(v.x, v.y);
        d[2 * j + 1] = __floats2half2_rn(v.z, v.w);
    }
}

// ---------------- router (fp32 logits + first-max argmax == jnp.argmax) ----------------
__global__ void router_kernel(const float* __restrict__ x, const float* __restrict__ Wr) {
    __shared__ float4 Wrs[NE * 256];
    int tid = threadIdx.x;
    const float4* Wr4 = (const float4*)Wr;
    for (int i = tid; i < NE * 256; i += 256) Wrs[i] = Wr4[i];
    __syncthreads();
    int warp = tid >> 5, lane = tid & 31;
    int n = blockIdx.x * 8 + warp;
    const float4* xr = (const float4*)(x + (size_t)n * HD);
    float acc[NE];
#pragma unroll
    for (int e = 0; e < NE; e++) acc[e] = 0.f;
#pragma unroll
    for (int j = 0; j < 8; j++) {
        float4 v = xr[j * 32 + lane];
#pragma unroll
        for (int e = 0; e < NE; e++) {
            float4 w = Wrs[e * 256 + j * 32 + lane];
            acc[e] += v.x * w.x + v.y * w.y + v.z * w.z + v.w * w.w;
        }
    }
#pragma unroll
    for (int e = 0; e < NE; e++)
#pragma unroll
        for (int o = 16; o > 0; o >>= 1) acc[e] += __shfl_xor_sync(0xffffffffu, acc[e], o);
    if (lane == 0) {
        int best = 0; float bv = acc[0];
#pragma unroll
        for (int e = 1; e < NE; e++) if (acc[e] > bv) { bv = acc[e]; best = e; }
        g_expert[n] = best;
        atomicAdd(&g_counts[best], 1);
    }
}

// ---------------- fused scan (padded) + scatter ----------------
__global__ void scatter_kernel() {
    int off[NE]; int a = 0;
#pragma unroll
    for (int e = 0; e < NE; e++) {
        off[e] = a;
        a += (g_counts[e] + 127) & ~127;    // pad each expert block to 128 rows
    }
    if (blockIdx.x == 0 && threadIdx.x == 0) {
#pragma unroll
        for (int e = 0; e < NE; e++) g_offsets[e] = off[e];
        g_offsets[NE] = a;                  // NP (multiple of 128, <= NPAD)
    }
    int t = blockIdx.x * 256 + threadIdx.x;
    if (t < NTOK) {
        int e = g_expert[t];
        int pos = off[e] + atomicAdd(&g_cursor[e], 1);
        g_perm[pos] = t;
    }
}

// ---------------- fp16 HMMA GEMM core (R12: hoisted addressing + frag double-buffer) ----------------
#define NST 3
#define A_BYT (128 * 128)            // 16KB
#define B_BYT (64 * 256)             // 16KB
#define ST_BYT (A_BYT + B_BYT)       // 32768
#define GEMM_SMEM (NST * ST_BYT + 512)

template <int EPI, bool PERM>
__device__ __forceinline__ void gemm_core(
    const __half* __restrict__ A, int lda,
    const __half* __restrict__ B, int ldb,
    const float* __restrict__ bias,
    int K,
    __half* __restrict__ outH, int ldc,
    int m0, int n0, char* smem, const int* __restrict__ perm)
{
    const int tid = threadIdx.x;
    const int lane = tid & 31, wid = tid >> 5;
    const int wm = wid >> 1, wn = wid & 1;      // 2 x 2 warp grid, 64x64 tiles

    const uint32_t smem_b = (uint32_t)__cvta_generic_to_shared(smem);

    int* s_perm = (int*)(smem + NST * ST_BYT);
    if (PERM) {
        int p = perm[m0 + tid];
        s_perm[tid] = (p < 0) ? 0 : p;          // pad rows -> row 0 (garbage, skipped later)
        __syncthreads();
    }

    // ---- precomputed ldmatrix offsets (stage-relative bytes) ----
    const int e7 = lane & 7;
    const int hA = lane >> 4;
    uint32_t A_row[4], A_xor[4], B_col[4];
#pragma unroll
    for (int mi = 0; mi < 4; mi++)
        A_row[mi] = (uint32_t)((wm * 64 + mi * 16 + (lane & 15)) << 7);
#pragma unroll
    for (int ks = 0; ks < 4; ks++)
        A_xor[ks] = (uint32_t)(((2 * ks + hA) ^ e7) << 4);
    {
        const int krl = lane & 15;              // B row within each 16-row ks-group
#pragma unroll
        for (int nj = 0; nj < 4; nj++) {
            int g = wn * 8 + nj * 2 + (lane >> 4);      // granule in [0,16)
            B_col[nj] = (uint32_t)(A_BYT + (krl << 8) + ((g ^ (krl & 7)) << 4));
        }
    }

    // ---- precomputed cp.async store offsets + base global pointers ----
    const int rA = tid >> 3, gA = tid & 7;          // A: rows rA+16i, i in [0,8)
    const int rB = tid >> 4, gB = tid & 15;         // B: rows rB+8i,  i in [0,8)
    const uint32_t stA = (uint32_t)((rA << 7) + ((gA ^ (rA & 7)) << 4));
    const uint32_t stB = (uint32_t)(A_BYT + (rB << 8) + ((gB ^ (rB & 7)) << 4));
    const __half* gB0 = B + (size_t)rB * ldb + n0 + (gB << 3);
    const __half* gA0;
    if (PERM) gA0 = A + (gA << 3);                  // row added per-i via s_perm
    else      gA0 = A + (size_t)(m0 + rA) * lda + (gA << 3);

    float acc[4][8][4];
#pragma unroll
    for (int i = 0; i < 4; i++)
#pragma unroll
        for (int j = 0; j < 8; j++)
#pragma unroll
            for (int k = 0; k < 4; k++) acc[i][j][k] = 0.f;

    const int nk = K >> 6;

    auto load_stage = [&](int s) {
        uint32_t base = smem_b + (s % NST) * ST_BYT;
        const int k0 = s << 6;
        const __half* ga = gA0 + k0;
        const __half* gb = gB0 + (size_t)k0 * ldb;
#pragma unroll
        for (int i = 0; i < 8; i++) {               // A: +16 rows per i = 2048B
            const __half* src = PERM
                ? ga + (size_t)s_perm[rA + (i << 4)] * lda
                : ga + ((size_t)(i << 4) * lda);
            cpa16(base + stA + (uint32_t)(i << 11), src);
        }
#pragma unroll
        for (int i = 0; i < 8; i++) {               // B: +8 rows per i = 2048B
            cpa16(base + stB + (uint32_t)(i << 11), gb + (size_t)(i << 3) * ldb);
        }
        asm volatile("cp.async.commit_group;" ::: "memory");
    };

    load_stage(0);
    load_stage(1);

    // double-buffered fragments
    uint32_t af[2][4][4];
    uint32_t bf[2][8][2];

    for (int kt = 0; kt < nk; kt++) {
        if (kt + 1 < nk) {
            asm volatile("cp.async.wait_group 1;" ::: "memory");
        } else {
            asm volatile("cp.async.wait_group 0;" ::: "memory");
        }
        __syncthreads();                            // stage kt ready AND buffer (kt+2)%3 free
        if (kt + 2 < nk) load_stage(kt + 2);

        const uint32_t base = smem_b + (kt % NST) * ST_BYT;

        // prefetch fragments for ks=0 (exposed once per kt)
        {
            const uint32_t abase = base + A_xor[0];
            const uint32_t bbase = base;
#pragma unroll
            for (int mi = 0; mi < 4; mi++)
                ldsm4(af[0][mi][0], af[0][mi][1], af[0][mi][2], af[0][mi][3],
                      abase + A_row[mi]);
#pragma unroll
            for (int nj = 0; nj < 4; nj++)
                ldsm4t(bf[0][2 * nj][0], bf[0][2 * nj][1], bf[0][2 * nj + 1][0], bf[0][2 * nj + 1][1],
                       bbase + B_col[nj]);
        }

#pragma unroll
        for (int ks = 0; ks < 4; ks++) {
            const int cur = ks & 1, nxt = cur ^ 1;
            if (ks < 3) {                           // prefetch ks+1 before consuming ks
                const uint32_t abase = base + A_xor[ks + 1];
                const uint32_t bbase = base + (uint32_t)((ks + 1) << 12);
#pragma unroll
                for (int mi = 0; mi < 4; mi++)
                    ldsm4(af[nxt][mi][0], af[nxt][mi][1], af[nxt][mi][2], af[nxt][mi][3],
                          abase + A_row[mi]);
#pragma unroll
                for (int nj = 0; nj < 4; nj++)
                    ldsm4t(bf[nxt][2 * nj][0], bf[nxt][2 * nj][1],
                           bf[nxt][2 * nj + 1][0], bf[nxt][2 * nj + 1][1],
                           bbase + B_col[nj]);
            }
#pragma unroll
            for (int mi = 0; mi < 4; mi++)
#pragma unroll
                for (int ni = 0; ni < 8; ni++)
                    mma16816(acc[mi][ni], af[cur][mi], bf[cur][ni]);
        }
    }

    // epilogue
    const int gq = lane >> 2, tq = lane & 3;
#pragma unroll
    for (int mi = 0; mi < 4; mi++) {
#pragma unroll
        for (int rr = 0; rr < 2; rr++) {
            int grow = m0 + wm * 64 + mi * 16 + gq + rr * 8;
#pragma unroll
            for (int ni = 0; ni < 8; ni++) {
                int col = n0 + wn * 64 + ni * 8 + tq * 2;
                float v0 = acc[mi][ni][rr * 2 + 0] + bias[col];
                float v1 = acc[mi][ni][rr * 2 + 1] + bias[col + 1];
                if (EPI == 1) { v0 = gelu_exact(v0); v1 = gelu_exact(v1); }
                *(__half2*)(outH + (size_t)grow * ldc + col) = __floats2half2_rn(v0, v1);
            }
        }
    }
}

// ---------------- grouped GEMM1 over padded flat grid (row-half chunked) ----------------
__global__ __launch_bounds__(128, 2) void gemm1_kernel(const float* __restrict__ b1, int ybase) {
    extern __shared__ char smem[];
    int m0 = (blockIdx.y + ybase) << 7;
    if (m0 >= g_offsets[NE]) return;
    int e = 0;
    while (m0 >= g_offsets[e + 1]) e++;          // padded offsets, monotone; e <= 7
    gemm_core<1, true>(g_xh, HD,
                       g_W1h + (size_t)e * HD * ID, ID,
                       b1 + (size_t)e * ID, HD,
                       g_inter, ID,
                       m0, blockIdx.x << 7, smem, g_perm);
}

// ---------------- dense GEMM2 over padded rows (row-half chunked) ----------------
__global__ __launch_bounds__(128, 2) void gemm2_kernel(const float* __restrict__ bo, int ybase) {
    extern __shared__ char smem[];
    int m0 = (blockIdx.y + ybase) << 7;
    if (m0 >= g_offsets[NE]) return;
    gemm_core<2, false>(g_inter, ID, g_Woh, HD, bo, ID,
                        g_yh, HD, m0, blockIdx.x << 7, smem, nullptr);
}

// ---------------- LayerNorm, exact fp32 residual, un-permute, skip pads ----------------
__global__ void ln_kernel(const float* __restrict__ x, const float* __restrict__ gamma,
                          const float* __restrict__ beta, float* __restrict__ out, int base) {
    int pos = blockIdx.x + base;
    int tok = g_perm[pos];
    if (tok < 0) return;                         // pad slot (or beyond NP)
    const __half2* yr = (const __half2*)(g_yh + (size_t)pos * HD);
    const float2* xr = (const float2*)(x + (size_t)tok * HD);
    int tid = threadIdx.x;
    float2 v[2]; float s = 0.f, s2 = 0.f;
#pragma unroll
    for (int j = 0; j < 2; j++) {
        int i = tid + j * 256;                   // half2 index, 512 pairs per row
        float2 yv = __half22float2(yr[i]);
        float2 xv = xr[i];
        v[j].x = yv.x + xv.x; v[j].y = yv.y + xv.y;
        s += v[j].x + v[j].y;
        s2 += v[j].x * v[j].x + v[j].y * v[j].y;
    }
    __shared__ float red[64];
#pragma unroll
    for (int o = 16; o > 0; o >>= 1) {
        s  += __shfl_xor_sync(0xffffffffu, s, o);
        s2 += __shfl_xor_sync(0xffffffffu, s2, o);
    }
    int w = tid >> 5;
    if ((tid & 31) == 0) { red[w] = s; red[32 + w] = s2; }
    __syncthreads();
    if (tid < 32) {
        float a = (tid < 8) ? red[tid] : 0.f;
        float b = (tid < 8) ? red[32 + tid] : 0.f;
#pragma unroll
        for (int o = 4; o > 0; o >>= 1) {
            a += __shfl_xor_sync(0xffffffffu, a, o);
            b += __shfl_xor_sync(0xffffffffu, b, o);
        }
        if (tid == 0) { red[0] = a; red[32] = b; }
    }
    __syncthreads();
    float mu = red[0] * (1.0f / HD);
    float var = red[32] * (1.0f / HD) - mu * mu;
    float rs = rsqrtf(var + 1e-12f);
    float2* orow = (float2*)(out + (size_t)tok * HD);
    const float2* g2 = (const float2*)gamma;
    const float2* b2 = (const float2*)beta;
#pragma unroll
    for (int j = 0; j < 2; j++) {
        int i = tid + j * 256;
        float2 gv = g2[i], bv = b2[i], o2;
        o2.x = (v[j].x - mu) * rs * gv.x + bv.x;
        o2.y = (v[j].y - mu) * rs * gv.y + bv.y;
        orow[i] = o2;
    }
}

// ---------------- launch: captured fork-join two-stream pipeline ----------------
extern "C" void kernel_launch(void* const* d_in, const int* in_sizes, int n_in,
                              void* d_out, int out_size) {
    const float* x     = (const float*)d_in[0];
    const float* Wr    = (const float*)d_in[1];
    const float* W1    = (const float*)d_in[2];
    const float* b1    = (const float*)d_in[3];
    const float* Wo    = (const float*)d_in[4];
    const float* bo    = (const float*)d_in[5];
    const float* gamma = (const float*)d_in[6];
    const float* beta  = (const float*)d_in[7];
    float* out = (float*)d_out;
    (void)in_sizes; (void)n_in; (void)out_size;

    static cudaStream_t s1 = nullptr;
    static cudaEvent_t evFork, evScat, evG1a, evG1b, evDone;
    if (!s1) {
        cudaStreamCreateWithFlags(&s1, cudaStreamNonBlocking);
        cudaEventCreateWithFlags(&evFork, cudaEventDisableTiming);
        cudaEventCreateWithFlags(&evScat, cudaEventDisableTiming);
        cudaEventCreateWithFlags(&evG1a, cudaEventDisableTiming);
        cudaEventCreateWithFlags(&evG1b, cudaEventDisableTiming);
        cudaEventCreateWithFlags(&evDone, cudaEventDisableTiming);
        cudaFuncSetAttribute(gemm1_kernel, cudaFuncAttributeMaxDynamicSharedMemorySize, GEMM_SMEM);
        cudaFuncSetAttribute(gemm2_kernel, cudaFuncAttributeMaxDynamicSharedMemorySize, GEMM_SMEM);
    }

    // fork s1 off the capture origin stream
    cudaEventRecord(evFork, 0);
    cudaStreamWaitEvent(s1, evFork, 0);

    // s1: routing chain (overlaps convert)
    init_kernel<<<36, 256, 0, s1>>>();
    router_kernel<<<1024, 256, 0, s1>>>(x, Wr);
    scatter_kernel<<<32, 256, 0, s1>>>();
    cudaEventRecord(evScat, s1);

    // stream 0: dtype conversion (35 us, hides the chain above)
    convert_kernel<<<45056, 256>>>((const float4*)W1, (const float4*)Wo, (const float4*)x);

    // join: gemm1 needs convert (stream order) + scatter (event)
    cudaStreamWaitEvent(0, evScat, 0);

    dim3 g1(ID / 128, YH, 1);
    gemm1_kernel<<<g1, 128, GEMM_SMEM>>>(b1, 0);          // h0
    cudaEventRecord(evG1a, 0);
    gemm1_kernel<<<g1, 128, GEMM_SMEM>>>(b1, YH);         // h1
    cudaEventRecord(evG1b, 0);

    // s1: gemm2+ln per half, pipelined against gemm1 h1
    dim3 g2(HD / 128, YH, 1);
    cudaStreamWaitEvent(s1, evG1a, 0);
    gemm2_kernel<<<g2, 128, GEMM_SMEM, s1>>>(bo, 0);      // h0 (overlaps gemm1 h1)
    ln_kernel<<<YH * 128, 256, 0, s1>>>(x, gamma, beta, out, 0);
    cudaStreamWaitEvent(s1, evG1b, 0);
    gemm2_kernel<<<g2, 128, GEMM_SMEM, s1>>>(bo, YH);     // h1
    ln_kernel<<<YH * 128, 256, 0, s1>>>(x, gamma, beta, out, YH * 128);
    cudaEventRecord(evDone, s1);

    // rejoin origin stream so capture ends with all work
    cudaStreamWaitEvent(0, evDone, 0);
}

// round 14
// speedup vs baseline: 1.0254x; 1.0254x over previous
#include <cuda_runtime.h>
#include <cuda_fp16.h>
#include <cstdint>
#include <math.h>

#define NTOK 8192
#define HD   1024
#define ID   4096
#define NE   8
#define NPAD 9216        // NTOK + NE*128 slack for per-expert padding

// ---------------- scratch (static device globals; no allocs) ----------------
__device__ __align__(256) __half g_W1h[(size_t)NE * HD * ID];   // 64 MB  [E][H][I]
__device__ __align__(256) __half g_Woh[(size_t)ID * HD];        // 8 MB   [I][H]
__device__ __align__(256) __half g_xh[(size_t)NTOK * HD];       // 16 MB  UNPERMUTED fp16 activations
__device__ __align__(256) __half g_inter[(size_t)NPAD * ID];    // 75.5 MB padded-permuted
__device__ __align__(256) __half g_yh[(size_t)NPAD * HD];       // 18.9 MB padded-permuted, +bo, fp16
__device__ int g_expert[NTOK];
__device__ int g_perm[NPAD];     // padded slots = -1
__device__ int g_counts[NE];
__device__ int g_offsets[NE + 1];  // PADDED offsets (each multiple of 128)
__device__ int g_cursor[NE];

// ---------------- helpers ----------------
__device__ __forceinline__ void cpa16(uint32_t s, const void* g) {
    asm volatile("cp.async.cg.shared.global [%0], [%1], 16;" :: "r"(s), "l"(g));
}
__device__ __forceinline__ void ldsm4(uint32_t& r0, uint32_t& r1, uint32_t& r2, uint32_t& r3, uint32_t a) {
    asm volatile("ldmatrix.sync.aligned.m8n8.x4.shared.b16 {%0,%1,%2,%3}, [%4];"
                 : "=r"(r0), "=r"(r1), "=r"(r2), "=r"(r3) : "r"(a));
}
__device__ __forceinline__ void ldsm4t(uint32_t& r0, uint32_t& r1, uint32_t& r2, uint32_t& r3, uint32_t a) {
    asm volatile("ldmatrix.sync.aligned.m8n8.x4.trans.shared.b16 {%0,%1,%2,%3}, [%4];"
                 : "=r"(r0), "=r"(r1), "=r"(r2), "=r"(r3) : "r"(a));
}
__device__ __forceinline__ void mma16816(float c[4], const uint32_t a[4], const uint32_t b[2]) {
    asm volatile("mma.sync.aligned.m16n8k16.row.col.f32.f16.f16.f32 "
                 "{%0,%1,%2,%3}, {%4,%5,%6,%7}, {%8,%9}, {%0,%1,%2,%3};"
                 : "+f"(c[0]), "+f"(c[1]), "+f"(c[2]), "+f"(c[3])
                 : "r"(a[0]), "r"(a[1]), "r"(a[2]), "r"(a[3]), "r"(b[0]), "r"(b[1]));
}
__device__ __forceinline__ float gelu_exact(float v) {
    return 0.5f * v * (1.0f + erff(v * 0.70710678118654752f));
}

// ---------------- launch 1: weight fp16 conversion (streaming) + init perm/counters ----------------
__global__ void convert_kernel(const float4* __restrict__ W1, const float4* __restrict__ Wo) {
    if (blockIdx.x < NPAD / 256) g_perm[blockIdx.x * 256 + threadIdx.x] = -1;
    if (blockIdx.x == 0 && threadIdx.x < NE) {
        g_counts[threadIdx.x] = 0; g_cursor[threadIdx.x] = 0;
    }
    size_t i = (size_t)blockIdx.x * blockDim.x + threadIdx.x;
    const size_t n1 = (size_t)NE * HD * ID / 4;      // 8388608
    const size_t n2 = (size_t)ID * HD / 4;           // 1048576
    if (i < n1) {
        float4 v = __ldcs(W1 + i);                   // streaming: no L2 retention
        __half2 h0 = __floats2half2_rn(v.x, v.y);
        __half2 h1 = __floats2half2_rn(v.z, v.w);
        uint32_t u0 = *(uint32_t*)&h0, u1 = *(uint32_t*)&h1;
        uint2 pk = make_uint2(u0, u1);
        __stcs((uint2*)g_W1h + i, pk);
    } else if (i < n1 + n2) {
        size_t j = i - n1;
        float4 v = __ldcs(Wo + j);
        __half2 h0 = __floats2half2_rn(v.x, v.y);
        __half2 h1 = __floats2half2_rn(v.z, v.w);
        uint32_t u0 = *(uint32_t*)&h0, u1 = *(uint32_t*)&h1;
        uint2 pk = make_uint2(u0, u1);
        __stcs((uint2*)g_Woh + j, pk);
    }
}

// ---------------- launch 2: router (fp32 logits + argmax) FUSED with x->fp16 conversion ----------------
__global__ void router_kernel(const float* __restrict__ x, const float* __restrict__ Wr) {
    __shared__ float4 Wrs[NE * 256];
    int tid = threadIdx.x;
    const float4* Wr4 = (const float4*)Wr;
    for (int i = tid; i < NE * 256; i += 256) Wrs[i] = Wr4[i];
    __syncthreads();
    int warp = tid >> 5, lane = tid & 31;
    int n = blockIdx.x * 8 + warp;
    const float4* xr = (const float4*)(x + (size_t)n * HD);
    __half2* hx = (__half2*)(g_xh + (size_t)n * HD);
    float acc[NE];
#pragma unroll
    for (int e = 0; e < NE; e++) acc[e] = 0.f;
#pragma unroll
    for (int j = 0; j < 8; j++) {
        int idx = j * 32 + lane;
        float4 v = xr[idx];
        hx[2 * idx]     = __floats2half2_rn(v.x, v.y);   // fused fp16 write
        hx[2 * idx + 1] = __floats2half2_rn(v.z, v.w);
#pragma unroll
        for (int e = 0; e < NE; e++) {
            float4 w = Wrs[e * 256 + idx];
            acc[e] += v.x * w.x + v.y * w.y + v.z * w.z + v.w * w.w;
        }
    }
#pragma unroll
    for (int e = 0; e < NE; e++)
#pragma unroll
        for (int o = 16; o > 0; o >>= 1) acc[e] += __shfl_xor_sync(0xffffffffu, acc[e], o);
    if (lane == 0) {
        int best = 0; float bv = acc[0];
#pragma unroll
        for (int e = 1; e < NE; e++) if (acc[e] > bv) { bv = acc[e]; best = e; }  // first-max == jnp.argmax
        g_expert[n] = best;
        atomicAdd(&g_counts[best], 1);
    }
}

// ---------------- launch 3: fused scan (padded) + scatter ----------------
__global__ void scatter_kernel() {
    int off[NE]; int a = 0;
#pragma unroll
    for (int e = 0; e < NE; e++) {
        off[e] = a;
        a += (g_counts[e] + 127) & ~127;    // pad each expert block to 128 rows
    }
    if (blockIdx.x == 0 && threadIdx.x == 0) {
#pragma unroll
        for (int e = 0; e < NE; e++) g_offsets[e] = off[e];
        g_offsets[NE] = a;                  // NP (multiple of 128, <= NPAD)
    }
    int t = blockIdx.x * 256 + threadIdx.x;
    if (t < NTOK) {
        int e = g_expert[t];
        int pos = off[e] + atomicAdd(&g_cursor[e], 1);
        g_perm[pos] = t;
    }
}

// ---------------- fp16 HMMA GEMM core (R12: hoisted addressing + frag double-buffer) ----------------
#define NST 3
#define A_BYT (128 * 128)            // 16KB
#define B_BYT (64 * 256)             // 16KB
#define ST_BYT (A_BYT + B_BYT)       // 32768
#define GEMM_SMEM (NST * ST_BYT + 512)

template <int EPI, bool PERM>
__device__ __forceinline__ void gemm_core(
    const __half* __restrict__ A, int lda,
    const __half* __restrict__ B, int ldb,
    const float* __restrict__ bias,
    int K,
    __half* __restrict__ outH, int ldc,
    int m0, int n0, char* smem, const int* __restrict__ perm)
{
    const int tid = threadIdx.x;
    const int lane = tid & 31, wid = tid >> 5;
    const int wm = wid >> 1, wn = wid & 1;      // 2 x 2 warp grid, 64x64 tiles

    const uint32_t smem_b = (uint32_t)__cvta_generic_to_shared(smem);

    int* s_perm = (int*)(smem + NST * ST_BYT);
    if (PERM) {
        int p = perm[m0 + tid];
        s_perm[tid] = (p < 0) ? 0 : p;          // pad rows -> row 0 (garbage, skipped later)
        __syncthreads();
    }

    // ---- precomputed ldmatrix offsets (stage-relative bytes) ----
    const int e7 = lane & 7;
    const int hA = lane >> 4;
    uint32_t A_row[4], A_xor[4], B_col[4];
#pragma unroll
    for (int mi = 0; mi < 4; mi++)
        A_row[mi] = (uint32_t)((wm * 64 + mi * 16 + (lane & 15)) << 7);
#pragma unroll
    for (int ks = 0; ks < 4; ks++)
        A_xor[ks] = (uint32_t)(((2 * ks + hA) ^ e7) << 4);
    {
        const int krl = lane & 15;              // B row within each 16-row ks-group
#pragma unroll
        for (int nj = 0; nj < 4; nj++) {
            int g = wn * 8 + nj * 2 + (lane >> 4);      // granule in [0,16)
            B_col[nj] = (uint32_t)(A_BYT + (krl << 8) + ((g ^ (krl & 7)) << 4));
        }
    }

    // ---- precomputed cp.async store offsets + base global pointers ----
    const int rA = tid >> 3, gA = tid & 7;          // A: rows rA+16i, i in [0,8)
    const int rB = tid >> 4, gB = tid & 15;         // B: rows rB+8i,  i in [0,8)
    const uint32_t stA = (uint32_t)((rA << 7) + ((gA ^ (rA & 7)) << 4));
    const uint32_t stB = (uint32_t)(A_BYT + (rB << 8) + ((gB ^ (rB & 7)) << 4));
    const __half* gB0 = B + (size_t)rB * ldb + n0 + (gB << 3);
    const __half* gA0;
    if (PERM) gA0 = A + (gA << 3);                  // row added per-i via s_perm
    else      gA0 = A + (size_t)(m0 + rA) * lda + (gA << 3);

    float acc[4][8][4];
#pragma unroll
    for (int i = 0; i < 4; i++)
#pragma unroll
        for (int j = 0; j < 8; j++)
#pragma unroll
            for (int k = 0; k < 4; k++) acc[i][j][k] = 0.f;

    const int nk = K >> 6;

    auto load_stage = [&](int s) {
        uint32_t base = smem_b + (s % NST) * ST_BYT;
        const int k0 = s << 6;
        const __half* ga = gA0 + k0;
        const __half* gb = gB0 + (size_t)k0 * ldb;
#pragma unroll
        for (int i = 0; i < 8; i++) {               // A: +16 rows per i = 2048B
            const __half* src = PERM
                ? ga + (size_t)s_perm[rA + (i << 4)] * lda
                : ga + ((size_t)(i << 4) * lda);
            cpa16(base + stA + (uint32_t)(i << 11), src);
        }
#pragma unroll
        for (int i = 0; i < 8; i++) {               // B: +8 rows per i = 2048B
            cpa16(base + stB + (uint32_t)(i << 11), gb + (size_t)(i << 3) * ldb);
        }
        asm volatile("cp.async.commit_group;" ::: "memory");
    };

    load_stage(0);
    load_stage(1);

    // double-buffered fragments
    uint32_t af[2][4][4];
    uint32_t bf[2][8][2];

    for (int kt = 0; kt < nk; kt++) {
        if (kt + 1 < nk) {
            asm volatile("cp.async.wait_group 1;" ::: "memory");
        } else {
            asm volatile("cp.async.wait_group 0;" ::: "memory");
        }
        __syncthreads();                            // stage kt ready AND buffer (kt+2)%3 free
        if (kt + 2 < nk) load_stage(kt + 2);

        const uint32_t base = smem_b + (kt % NST) * ST_BYT;

        // prefetch fragments for ks=0 (exposed once per kt)
        {
            const uint32_t abase = base + A_xor[0];
            const uint32_t bbase = base;
#pragma unroll
            for (int mi = 0; mi < 4; mi++)
                ldsm4(af[0][mi][0], af[0][mi][1], af[0][mi][2], af[0][mi][3],
                      abase + A_row[mi]);
#pragma unroll
            for (int nj = 0; nj < 4; nj++)
                ldsm4t(bf[0][2 * nj][0], bf[0][2 * nj][1], bf[0][2 * nj + 1][0], bf[0][2 * nj + 1][1],
                       bbase + B_col[nj]);
        }

#pragma unroll
        for (int ks = 0; ks < 4; ks++) {
            const int cur = ks & 1, nxt = cur ^ 1;
            if (ks < 3) {                           // prefetch ks+1 before consuming ks
                const uint32_t abase = base + A_xor[ks + 1];
                const uint32_t bbase = base + (uint32_t)((ks + 1) << 12);
#pragma unroll
                for (int mi = 0; mi < 4; mi++)
                    ldsm4(af[nxt][mi][0], af[nxt][mi][1], af[nxt][mi][2], af[nxt][mi][3],
                          abase + A_row[mi]);
#pragma unroll
                for (int nj = 0; nj < 4; nj++)
                    ldsm4t(bf[nxt][2 * nj][0], bf[nxt][2 * nj][1],
                           bf[nxt][2 * nj + 1][0], bf[nxt][2 * nj + 1][1],
                           bbase + B_col[nj]);
            }
#pragma unroll
            for (int mi = 0; mi < 4; mi++)
#pragma unroll
                for (int ni = 0; ni < 8; ni++)
                    mma16816(acc[mi][ni], af[cur][mi], bf[cur][ni]);
        }
    }

    // epilogue
    const int gq = lane >> 2, tq = lane & 3;
#pragma unroll
    for (int mi = 0; mi < 4; mi++) {
#pragma unroll
        for (int rr = 0; rr < 2; rr++) {
            int grow = m0 + wm * 64 + mi * 16 + gq + rr * 8;
#pragma unroll
            for (int ni = 0; ni < 8; ni++) {
                int col = n0 + wn * 64 + ni * 8 + tq * 2;
                float v0 = acc[mi][ni][rr * 2 + 0] + bias[col];
                float v1 = acc[mi][ni][rr * 2 + 1] + bias[col + 1];
                if (EPI == 1) { v0 = gelu_exact(v0); v1 = gelu_exact(v1); }
                *(__half2*)(outH + (size_t)grow * ldc + col) = __floats2half2_rn(v0, v1);
            }
        }
    }
}

// ---------------- launch 4: grouped GEMM1 over padded flat grid ----------------
__global__ __launch_bounds__(128, 2) void gemm1_kernel(const float* __restrict__ b1) {
    extern __shared__ char smem[];
    int m0 = blockIdx.y << 7;
    if (m0 >= g_offsets[NE]) return;
    int e = 0;
    while (m0 >= g_offsets[e + 1]) e++;          // padded offsets, monotone; e <= 7
    gemm_core<1, true>(g_xh, HD,
                       g_W1h + (size_t)e * HD * ID, ID,
                       b1 + (size_t)e * ID, HD,
                       g_inter, ID,
                       m0, blockIdx.x << 7, smem, g_perm);
}

// ---------------- launch 5: dense GEMM2 over padded rows ----------------
__global__ __launch_bounds__(128, 2) void gemm2_kernel(const float* __restrict__ bo) {
    extern __shared__ char smem[];
    int m0 = blockIdx.y << 7;
    if (m0 >= g_offsets[NE]) return;
    gemm_core<2, false>(g_inter, ID, g_Woh, HD, bo, ID,
                        g_yh, HD, m0, blockIdx.x << 7, smem, nullptr);
}

// ---------------- launch 6: LayerNorm, exact fp32 residual, un-permute, skip pads ----------------
__global__ void ln_kernel(const float* __restrict__ x, const float* __restrict__ gamma,
                          const float* __restrict__ beta, float* __restrict__ out) {
    int pos = blockIdx.x;
    int tok = g_perm[pos];
    if (tok < 0) return;                         // pad slot (or beyond NP)
    const __half2* yr = (const __half2*)(g_yh + (size_t)pos * HD);
    const float2* xr = (const float2*)(x + (size_t)tok * HD);
    int tid = threadIdx.x;
    float2 v[2]; float s = 0.f, s2 = 0.f;
#pragma unroll
    for (int j = 0; j < 2; j++) {
        int i = tid + j * 256;                   // half2 index, 512 pairs per row
        float2 yv = __half22float2(yr[i]);
        float2 xv = xr[i];
        v[j].x = yv.x + xv.x; v[j].y = yv.y + xv.y;
        s += v[j].x + v[j].y;
        s2 += v[j].x * v[j].x + v[j].y * v[j].y;
    }
    __shared__ float red[64];
#pragma unroll
    for (int o = 16; o > 0; o >>= 1) {
        s  += __shfl_xor_sync(0xffffffffu, s, o);
        s2 += __shfl_xor_sync(0xffffffffu, s2, o);
    }
    int w = tid >> 5;
    if ((tid & 31) == 0) { red[w] = s; red[32 + w] = s2; }
    __syncthreads();
    if (tid < 32) {
        float a = (tid < 8) ? red[tid] : 0.f;
        float b = (tid < 8) ? red[32 + tid] : 0.f;
#pragma unroll
        for (int o = 4; o > 0; o >>= 1) {
            a += __shfl_xor_sync(0xffffffffu, a, o);
            b += __shfl_xor_sync(0xffffffffu, b, o);
        }
        if (tid == 0) { red[0] = a; red[32] = b; }
    }
    __syncthreads();
    float mu = red[0] * (1.0f / HD);
    float var = red[32] * (1.0f / HD) - mu * mu;
    float rs = rsqrtf(var + 1e-12f);
    float2* orow = (float2*)(out + (size_t)tok * HD);
    const float2* g2 = (const float2*)gamma;
    const float2* b2 = (const float2*)beta;
#pragma unroll
    for (int j = 0; j < 2; j++) {
        int i = tid + j * 256;
        float2 gv = g2[i], bv = b2[i], o2;
        o2.x = (v[j].x - mu) * rs * gv.x + bv.x;
        o2.y = (v[j].y - mu) * rs * gv.y + bv.y;
        orow[i] = o2;
    }
}

// ---------------- launch: sequential single stream ----------------
extern "C" void kernel_launch(void* const* d_in, const int* in_sizes, int n_in,
                              void* d_out, int out_size) {
    const float* x     = (const float*)d_in[0];
    const float* Wr    = (const float*)d_in[1];
    const float* W1    = (const float*)d_in[2];
    const float* b1    = (const float*)d_in[3];
    const float* Wo    = (const float*)d_in[4];
    const float* bo    = (const float*)d_in[5];
    const float* gamma = (const float*)d_in[6];
    const float* beta  = (const float*)d_in[7];
    float* out = (float*)d_out;
    (void)in_sizes; (void)n_in; (void)out_size;

    cudaFuncSetAttribute(gemm1_kernel, cudaFuncAttributeMaxDynamicSharedMemorySize, GEMM_SMEM);
    cudaFuncSetAttribute(gemm2_kernel, cudaFuncAttributeMaxDynamicSharedMemorySize, GEMM_SMEM);

    convert_kernel<<<36864, 256>>>((const float4*)W1, (const float4*)Wo);   // 1 (weights only)
    router_kernel<<<1024, 256>>>(x, Wr);                                    // 2 (+x conversion)
    scatter_kernel<<<32, 256>>>();                                          // 3

    dim3 g1(ID / 128, NPAD / 128, 1);    // 32 x 72, flat padded grid; all live tiles full
    gemm1_kernel<<<g1, 128, GEMM_SMEM>>>(b1);                               // 4 (ncu target)

    dim3 g2(HD / 128, NPAD / 128, 1);    // 8 x 72
    gemm2_kernel<<<g2, 128, GEMM_SMEM>>>(bo);                               // 5

    ln_kernel<<<NPAD, 256>>>(x, gamma, beta, out);                          // 6
}